// round 12
// baseline (speedup 1.0000x reference)
#include <cuda_runtime.h>
#include <cuda_bf16.h>
#include <cstdint>
#include <math.h>

#define NN   50000
#define EE   600000
#define INF_ 512
#define HH   128
#define H3   384
#define BB   64
#define MT   ((NN + 127) / 128)      // 391
#define SEGN (4*NN)                  // 200000 segments (view, dst)
#define SCAN_BLKS ((SEGN + 1023)/1024)  // 196
#define GRU_GRID ((NN + 63)/64)      // 782

// ---------------- device scratch (no allocs allowed) ----------------
__device__ float g_h0   [(size_t)NN*HH];
__device__ float g_hallA[(size_t)4*NN*HH];
__device__ float g_hallB[(size_t)4*NN*HH];
__device__ float g_proj [(size_t)NN*HH];
__device__ float g_q    [(size_t)NN*HH];
__device__ float g_qk   [(size_t)NN*HH];
__device__ float g_fused[(size_t)NN*HH];
__device__ float g_psum[BB*HH];
__device__ unsigned g_pmax[BB*HH];
__device__ float g_cnt [BB];

// CSR build
__device__ int g_deg   [SEGN];
__device__ int g_scanT [SEGN];
__device__ int g_part  [SCAN_BLKS];
__device__ int g_partS [SCAN_BLKS];
__device__ int g_rowptr[SEGN + 1];
__device__ int g_woff  [SEGN];
__device__ int g_csrsrc[EE];

// ---------------- B fragment images (hi/lo bf16 packed per mma lane) ----------------
#define OFF_WHH  0
#define OFF_PROJ 49152
#define OFF_QW   65536
#define OFF_KWT  69632
#define FRAG_TOTAL 73728
__device__ uint4 g_frag[FRAG_TOTAL];
// Wcomb[v][i] = ggnn_w[v,i] @ wih[v]^T fragment images: 16 * 12288 uint4
__device__ uint4 g_fragW[16u*12288u];

// edge type -> view (VIEWS = [[0,9,10],[1,2,3],[4,5,6],[7,8,11,12]])
__constant__ int c_v_of_t[13] = {0,1,1,1,2,2,2,3,3,0,0,3,3};

// ---------------- helpers ----------------
__device__ __forceinline__ uint32_t packbf(float a, float b){
    __nv_bfloat162 t = __halves2bfloat162(__float2bfloat16(a), __float2bfloat16(b));
    return *reinterpret_cast<uint32_t*>(&t);
}
__device__ __forceinline__ uint2 packhl(float2 v){
    float hx = __bfloat162float(__float2bfloat16(v.x));
    float hy = __bfloat162float(__float2bfloat16(v.y));
    return make_uint2(packbf(v.x, v.y), packbf(v.x - hx, v.y - hy));
}
__device__ __forceinline__ unsigned fenc(float f){
    unsigned b = __float_as_uint(f);
    return (b & 0x80000000u) ? ~b : (b | 0x80000000u);
}
__device__ __forceinline__ float fdec(unsigned u){
    return __uint_as_float((u & 0x80000000u) ? (u & 0x7fffffffu) : ~u);
}
__device__ __forceinline__ float sigm(float x){ return 1.f/(1.f + expf(-x)); }

#define MMA16816(d, a, b0_, b1_) \
  asm volatile("mma.sync.aligned.m16n8k16.row.col.f32.bf16.bf16.f32 " \
    "{%0,%1,%2,%3}, {%4,%5,%6,%7}, {%8,%9}, {%0,%1,%2,%3};" \
    : "+f"((d)[0]), "+f"((d)[1]), "+f"((d)[2]), "+f"((d)[3]) \
    : "r"((a)[0]), "r"((a)[1]), "r"((a)[2]), "r"((a)[3]), "r"(b0_), "r"(b1_))

// ---------------- CSR build ----------------
__global__ void csr_zero(){
    int i = blockIdx.x*blockDim.x + threadIdx.x;
    if (i < SEGN) g_deg[i] = 0;
}
__global__ void csr_count(const int* __restrict__ ei, const int* __restrict__ et){
    int e = blockIdx.x*blockDim.x + threadIdx.x;
    if (e >= EE) return;
    int v = c_v_of_t[et[e]];
    atomicAdd(&g_deg[v*NN + ei[EE + e]], 1);
}
__global__ void csr_scan1(){
    __shared__ int sm[1024];
    int t = threadIdx.x, b = blockIdx.x;
    int i = b*1024 + t;
    int v = (i < SEGN) ? g_deg[i] : 0;
    sm[t] = v;
    __syncthreads();
    #pragma unroll
    for (int o = 1; o < 1024; o <<= 1){
        int add = (t >= o) ? sm[t - o] : 0;
        __syncthreads();
        sm[t] += add;
        __syncthreads();
    }
    if (i < SEGN) g_scanT[i] = sm[t];
    if (t == 1023) g_part[b] = sm[1023];
}
__global__ void csr_scan2(){
    __shared__ int sm[SCAN_BLKS];
    int t = threadIdx.x;
    if (t < SCAN_BLKS) sm[t] = g_part[t];
    __syncthreads();
    if (t == 0){
        int run = 0;
        for (int i = 0; i < SCAN_BLKS; i++){ run += sm[i]; g_partS[i] = run; }
    }
}
__global__ void csr_scan3(){
    int i = blockIdx.x*blockDim.x + threadIdx.x;
    if (i >= SEGN) return;
    int b = i >> 10;
    int base = (b > 0) ? g_partS[b-1] : 0;
    int excl = base + g_scanT[i] - g_deg[i];
    g_rowptr[i] = excl;
    g_woff[i]   = excl;
    if (i == 0) g_rowptr[SEGN] = EE;
}
__global__ void csr_fill(const int* __restrict__ ei, const int* __restrict__ et){
    int e = blockIdx.x*blockDim.x + threadIdx.x;
    if (e >= EE) return;
    int v = c_v_of_t[et[e]];
    int pos = atomicAdd(&g_woff[v*NN + ei[EE + e]], 1);
    g_csrsrc[pos] = ei[e];
}

// ---------------- prep: whh/proj/qw/kw^T -> fragment images (hi/lo bf16) ----------------
__global__ void prep_frags(const float* __restrict__ whh, const float* __restrict__ projw,
                           const float* __restrict__ qw, const float* __restrict__ kw){
    int tid = blockIdx.x*blockDim.x + threadIdx.x;
    if (tid >= FRAG_TOTAL) return;
    const float* M; int NT, rel; bool tr;
    if (tid < OFF_PROJ){       int q = tid;          rel = q % 12288; M = whh + (size_t)(q/12288)*49152; NT = 48; tr = true; }
    else if (tid < OFF_QW){    rel = tid-OFF_PROJ; M = projw; NT = 16; tr = false; }
    else if (tid < OFF_KWT){   rel = tid-OFF_QW;   M = qw;    NT = 16; tr = false; }
    else{                      rel = tid-OFF_KWT;  M = kw;    NT = 16; tr = true; }  // kw^T for qk
    int lane = rel & 31, t2 = rel >> 5;
    int nt = t2 % NT, kt = t2 / NT;
    int n = nt*8 + (lane >> 2), k0 = kt*16 + (lane & 3)*2;
    float v[4];
    #pragma unroll
    for (int q = 0; q < 4; q++){
        int k = k0 + (q >> 1)*8 + (q & 1);
        v[q] = tr ? M[(size_t)n*128 + k] : M[(size_t)k*128 + n];
    }
    float h[4], l[4];
    #pragma unroll
    for (int q = 0; q < 4; q++){
        h[q] = __bfloat162float(__float2bfloat16(v[q]));
        l[q] = v[q] - h[q];
    }
    uint4 o;
    o.x = packbf(h[0], h[1]); o.y = packbf(h[2], h[3]);
    o.z = packbf(l[0], l[1]); o.w = packbf(l[2], l[3]);
    g_frag[tid] = o;
}

// ---------------- Wcomb = ggnn[v,i] @ wih[v]^T -> fragment image ----------------
__global__ __launch_bounds__(256)
void wcomb_prep(const float* __restrict__ ggnn, const float* __restrict__ wih){
    extern __shared__ float s[];
    float* As = s;                 // [j][k] pitch 129
    float* Ws = s + 128*129;       // [j][c] pitch 129
    float* Cs = s + 2*128*129;     // [k][c] pitch 128
    int vi = blockIdx.x, cblk = blockIdx.y, v = vi >> 2;
    const float* A = ggnn + (size_t)vi*16384;                       // A[k][j]
    const float* W = wih + ((size_t)v*H3 + cblk*128)*128;           // W[c][j]
    int tid = threadIdx.x;
    for (int i = tid; i < 16384; i += 256){
        int r = i >> 7, j = i & 127;
        As[j*129 + r] = A[i];
        Ws[j*129 + r] = W[i];
    }
    __syncthreads();
    int tx = tid & 15, ty = tid >> 4;
    float acc[8][8];
    #pragma unroll
    for (int a = 0; a < 8; a++)
        #pragma unroll
        for (int b = 0; b < 8; b++) acc[a][b] = 0.f;
    for (int j = 0; j < 128; j++){
        float av[8], wv[8];
        #pragma unroll
        for (int q = 0; q < 8; q++){
            av[q] = As[j*129 + ty*8 + q];
            wv[q] = Ws[j*129 + tx*8 + q];
        }
        #pragma unroll
        for (int a = 0; a < 8; a++)
            #pragma unroll
            for (int b = 0; b < 8; b++) acc[a][b] += av[a]*wv[b];
    }
    #pragma unroll
    for (int a = 0; a < 8; a++)
        #pragma unroll
        for (int b = 0; b < 8; b++)
            Cs[(ty*8+a)*128 + tx*8+b] = acc[a][b];
    __syncthreads();
    uint4* dst = g_fragW + (size_t)vi*12288;
    for (int it = tid; it < 4096; it += 256){
        int lane = it & 31, t2 = it >> 5;
        int lnt = t2 & 15, kt = t2 >> 4;
        int c = lnt*8 + (lane >> 2);
        int k0 = kt*16 + (lane & 3)*2;
        float vq[4], h[4], l[4];
        #pragma unroll
        for (int q = 0; q < 4; q++){
            int k = k0 + (q >> 1)*8 + (q & 1);
            vq[q] = Cs[k*128 + c];
            h[q] = __bfloat162float(__float2bfloat16(vq[q]));
            l[q] = vq[q] - h[q];
        }
        uint4 o;
        o.x = packbf(h[0], h[1]); o.y = packbf(h[2], h[3]);
        o.z = packbf(l[0], l[1]); o.w = packbf(l[2], l[3]);
        int ntg = cblk*16 + lnt;
        dst[((size_t)(kt*48 + ntg))*32 + lane] = o;
    }
}

// ---------------- HMMA GEMM (proj / q / qk) ----------------
__global__ __launch_bounds__(256)
void gemm_mma(const float* __restrict__ A, int lda, int M,
              const uint4* __restrict__ frag, int NT, int KT,
              const float* __restrict__ bias, float* __restrict__ C,
              int ldc, int act){
    int tid = threadIdx.x, wid = tid >> 5, lane = tid & 31;
    int wm = wid >> 1, wn = wid & 1;
    int gid = lane >> 2, tig = lane & 3;
    int rowBase = blockIdx.x*128 + wm*32 + gid;
    int ntG0 = blockIdx.y*16 + wn*8;

    float acc[2][8][4];
    #pragma unroll
    for (int mt = 0; mt < 2; mt++)
        #pragma unroll
        for (int nt = 0; nt < 8; nt++)
            #pragma unroll
            for (int q = 0; q < 4; q++) acc[mt][nt][q] = 0.f;

    float2 ax[2][4];
    auto loadA = [&](int kt){
        #pragma unroll
        for (int mt = 0; mt < 2; mt++){
            int r = rowBase + mt*16;
            int k = kt*16 + tig*2;
            bool p0 = (r < M), p1 = (r + 8 < M);
            const float* base0 = A + (size_t)r*lda + k;
            const float* base1 = A + (size_t)(r+8)*lda + k;
            ax[mt][0] = p0 ? *(const float2*)(base0)     : make_float2(0.f, 0.f);
            ax[mt][1] = p1 ? *(const float2*)(base1)     : make_float2(0.f, 0.f);
            ax[mt][2] = p0 ? *(const float2*)(base0 + 8) : make_float2(0.f, 0.f);
            ax[mt][3] = p1 ? *(const float2*)(base1 + 8) : make_float2(0.f, 0.f);
        }
    };
    loadA(0);
    uint4 bcur = frag[((size_t)(0*NT + ntG0))*32 + lane];

    for (int kt = 0; kt < KT; kt++){
        uint32_t Ah[2][4], Al[2][4];
        #pragma unroll
        for (int mt = 0; mt < 2; mt++){
            #pragma unroll
            for (int q = 0; q < 4; q++){
                float2 vv = ax[mt][q];
                float hx = __bfloat162float(__float2bfloat16(vv.x));
                float hy = __bfloat162float(__float2bfloat16(vv.y));
                Ah[mt][q] = packbf(vv.x, vv.y);
                Al[mt][q] = packbf(vv.x - hx, vv.y - hy);
            }
        }
        if (kt + 1 < KT) loadA(kt + 1);
        #pragma unroll
        for (int nt = 0; nt < 8; nt++){
            uint4 bn;
            if (nt < 7)           bn = frag[((size_t)(kt*NT + ntG0 + nt + 1))*32 + lane];
            else if (kt + 1 < KT) bn = frag[((size_t)((kt+1)*NT + ntG0))*32 + lane];
            else                  bn = bcur;
            #pragma unroll
            for (int mt = 0; mt < 2; mt++){
                MMA16816(acc[mt][nt], Ah[mt], bcur.x, bcur.y);
                MMA16816(acc[mt][nt], Ah[mt], bcur.z, bcur.w);
                MMA16816(acc[mt][nt], Al[mt], bcur.x, bcur.y);
            }
            bcur = bn;
        }
    }

    #pragma unroll
    for (int nt = 0; nt < 8; nt++){
        int col = (ntG0 + nt)*8 + tig*2;
        float b0 = 0.f, b1 = 0.f;
        if (bias){ b0 = bias[col]; b1 = bias[col + 1]; }
        #pragma unroll
        for (int mt = 0; mt < 2; mt++){
            int r = rowBase + mt*16;
            float v0 = acc[mt][nt][0] + b0, v1 = acc[mt][nt][1] + b1;
            float v2 = acc[mt][nt][2] + b0, v3 = acc[mt][nt][3] + b1;
            if (act == 1){ v0 = tanhf(v0); v1 = tanhf(v1); v2 = tanhf(v2); v3 = tanhf(v3); }
            if (r < M)     *(float2*)(C + (size_t)r*ldc + col)     = make_float2(v0, v1);
            if (r + 8 < M) *(float2*)(C + (size_t)(r+8)*ldc + col) = make_float2(v2, v3);
        }
    }
}

// ---------------- fused GRU cell v3: gate-partitioned + B double-buffering ------
// Warps: 16 = 4 gate-groups x 4 column-slices. B fragments for kt+1 are loaded
// before issuing kt's MMAs so the 4 dependent LDG.128s never stall the tensor pipe.
#define GPASS(SA, FP, GATE, ACC) do { \
  const uint4* _bb = (FP) + ((size_t)((GATE)*16 + sub*4))*32 + lane; \
  uint4 b0 = _bb[0], b1 = _bb[32], b2 = _bb[64], b3 = _bb[96]; \
  _Pragma("unroll 1") \
  for (int kt = 0; kt < 8; kt++){ \
    uint4 n0 = b0, n1 = b1, n2 = b2, n3 = b3; \
    if (kt < 7){ \
      const uint4* _nb = _bb + (size_t)(kt + 1)*1536; \
      n0 = _nb[0]; n1 = _nb[32]; n2 = _nb[64]; n3 = _nb[96]; \
    } \
    _Pragma("unroll") \
    for (int mt = 0; mt < 4; mt++){ \
      uint4 fh = (SA)[(mt*8 + kt)*32 + lane]; \
      uint4 fl = (SA)[1024 + (mt*8 + kt)*32 + lane]; \
      uint32_t AH_[4] = {fh.x, fh.y, fh.z, fh.w}; \
      uint32_t AL_[4] = {fl.x, fl.y, fl.z, fl.w}; \
      MMA16816(ACC[mt][0], AH_, b0.x, b0.y); \
      MMA16816(ACC[mt][0], AH_, b0.z, b0.w); \
      MMA16816(ACC[mt][0], AL_, b0.x, b0.y); \
      MMA16816(ACC[mt][1], AH_, b1.x, b1.y); \
      MMA16816(ACC[mt][1], AH_, b1.z, b1.w); \
      MMA16816(ACC[mt][1], AL_, b1.x, b1.y); \
      MMA16816(ACC[mt][2], AH_, b2.x, b2.y); \
      MMA16816(ACC[mt][2], AH_, b2.z, b2.w); \
      MMA16816(ACC[mt][2], AL_, b2.x, b2.y); \
      MMA16816(ACC[mt][3], AH_, b3.x, b3.y); \
      MMA16816(ACC[mt][3], AH_, b3.z, b3.w); \
      MMA16816(ACC[mt][3], AL_, b3.x, b3.y); \
    } \
    b0 = n0; b1 = n1; b2 = n2; b3 = n3; \
  } } while(0)

__global__ __launch_bounds__(512)
void gru_fused(const float* __restrict__ Hin, float* __restrict__ Hout,
               const uint4* __restrict__ wcF, const uint4* __restrict__ whhF,
               const float* __restrict__ bih, const float* __restrict__ bhh,
               const int* __restrict__ rowptrB, size_t hinStride){
    extern __shared__ char sm[];
    uint4* sAg   = (uint4*)sm;             // frag G hi/lo: 2048 uint4 (32KB) | post-MMA: gate r
    uint4* sH    = (uint4*)(sm + 32768);   // frag h hi/lo (32KB)            | post-MMA: gate z
    float* sHval = (float*)(sm + 65536);   // 64*128 fp32 (32KB), live to end
    float* sAval = (float*)(sm + 98304);   // 64*128 fp32 (32KB)             | post-MMA: gate inn
    float* sbias = (float*)(sm + 131072);  // 512 floats (2KB)
    float* sGn   = (float*)(sm + 133120);  // gate hn (32KB)
    float* sGr   = (float*)sm;
    float* sGz   = (float*)(sm + 32768);
    float* sGi   = sAval;
    int tid = threadIdx.x, wid = tid >> 5, lane = tid & 31;
    int gid = lane >> 2, tig = lane & 3;

    int v   = blockIdx.x / GRU_GRID;
    int blk = blockIdx.x % GRU_GRID;
    int m0 = blk*64;
    const float* Hsrc = Hin + (size_t)v * hinStride;
    Hout   += (size_t)v * NN * HH;
    wcF    += (size_t)v * 49152;
    whhF   += (size_t)v * 12288;
    bih    += v * H3;
    bhh    += v * H3;
    const int* rowptr = rowptrB + v * NN;

    if (tid < 128){
        sbias[tid]     = bih[tid]     + bhh[tid];        // r
        sbias[128+tid] = bih[128+tid] + bhh[128+tid];    // z
        sbias[256+tid] = bih[256+tid];                   // inn
        sbias[384+tid] = bhh[256+tid];                   // hn
    }
    // load h tile
    for (int it = tid; it < 64*32; it += 512){
        int r = it >> 5, c4 = it & 31;
        float4 hv = make_float4(0.f,0.f,0.f,0.f);
        if (m0 + r < NN) hv = *(const float4*)(Hsrc + (size_t)(m0+r)*HH + c4*4);
        *(float4*)(sHval + r*128 + c4*4) = hv;
    }
    // CSR gather of h rows -> sAval
    for (int rr = wid; rr < 64; rr += 16){
        int grow = m0 + rr;
        float4 acc = make_float4(0.f,0.f,0.f,0.f);
        if (grow < NN){
            int s = rowptr[grow], e = rowptr[grow + 1];
            int idx = s;
            while (idx + 4 <= e){
                int a0 = g_csrsrc[idx], a1 = g_csrsrc[idx+1];
                int a2 = g_csrsrc[idx+2], a3 = g_csrsrc[idx+3];
                float4 v0 = *(const float4*)(Hsrc + (size_t)a0*HH + lane*4);
                float4 v1 = *(const float4*)(Hsrc + (size_t)a1*HH + lane*4);
                float4 v2 = *(const float4*)(Hsrc + (size_t)a2*HH + lane*4);
                float4 v3 = *(const float4*)(Hsrc + (size_t)a3*HH + lane*4);
                acc.x += v0.x + v1.x + v2.x + v3.x;
                acc.y += v0.y + v1.y + v2.y + v3.y;
                acc.z += v0.z + v1.z + v2.z + v3.z;
                acc.w += v0.w + v1.w + v2.w + v3.w;
                idx += 4;
            }
            while (idx < e){
                int a0 = g_csrsrc[idx];
                float4 v0 = *(const float4*)(Hsrc + (size_t)a0*HH + lane*4);
                acc.x += v0.x; acc.y += v0.y; acc.z += v0.z; acc.w += v0.w;
                idx++;
            }
        }
        *(float4*)(sAval + rr*128 + lane*4) = acc;
    }
    __syncthreads();
    // pack G + h into bf16 hi/lo fragments
    for (int it = tid; it < 1024; it += 512){
        int mt = it >> 8, kt = (it >> 5) & 7, ln = it & 31;
        int g = ln >> 2, tg = ln & 3;
        int r0 = mt*16 + g, r1 = r0 + 8;
        int k = kt*16 + tg*2;
        float2 a00 = *(const float2*)(sAval + r0*128 + k);
        float2 a01 = *(const float2*)(sAval + r0*128 + k + 8);
        float2 a10 = *(const float2*)(sAval + r1*128 + k);
        float2 a11 = *(const float2*)(sAval + r1*128 + k + 8);
        uint2 p0 = packhl(a00), p1 = packhl(a10), p2 = packhl(a01), p3 = packhl(a11);
        sAg[(mt*8 + kt)*32 + ln]        = make_uint4(p0.x, p1.x, p2.x, p3.x);
        sAg[1024 + (mt*8 + kt)*32 + ln] = make_uint4(p0.y, p1.y, p2.y, p3.y);
        float2 h00 = *(const float2*)(sHval + r0*128 + k);
        float2 h01 = *(const float2*)(sHval + r0*128 + k + 8);
        float2 h10 = *(const float2*)(sHval + r1*128 + k);
        float2 h11 = *(const float2*)(sHval + r1*128 + k + 8);
        uint2 q0 = packhl(h00), q1 = packhl(h10), q2 = packhl(h01), q3 = packhl(h11);
        sH[(mt*8 + kt)*32 + ln]        = make_uint4(q0.x, q1.x, q2.x, q3.x);
        sH[1024 + (mt*8 + kt)*32 + ln] = make_uint4(q0.y, q1.y, q2.y, q3.y);
    }
    __syncthreads();

    // MMA phase: warp = (gate group g, column slice sub)
    int g = wid >> 2, sub = wid & 3;
    float acc[4][4][4];
    #pragma unroll
    for (int mt = 0; mt < 4; mt++)
        #pragma unroll
        for (int nt = 0; nt < 4; nt++)
            #pragma unroll
            for (int q = 0; q < 4; q++) acc[mt][nt][q] = 0.f;

    if (g == 0){ GPASS(sAg, wcF, 0, acc); GPASS(sH, whhF, 0, acc); }
    else if (g == 1){ GPASS(sAg, wcF, 1, acc); GPASS(sH, whhF, 1, acc); }
    else if (g == 2){ GPASS(sAg, wcF, 2, acc); }
    else            { GPASS(sH, whhF, 2, acc); }

    __syncthreads();   // all fragment reads done; safe to overwrite sAg/sH/sAval

    // write gate accumulators to smem [64][128] per gate
    {
        float* gout = (g == 0) ? sGr : (g == 1) ? sGz : (g == 2) ? sGi : sGn;
        #pragma unroll
        for (int mt = 0; mt < 4; mt++){
            #pragma unroll
            for (int nt = 0; nt < 4; nt++){
                int col = sub*32 + nt*8 + tig*2;
                int r0 = mt*16 + gid;
                *(float2*)(gout + r0*128 + col)     = make_float2(acc[mt][nt][0], acc[mt][nt][1]);
                *(float2*)(gout + (r0+8)*128 + col) = make_float2(acc[mt][nt][2], acc[mt][nt][3]);
            }
        }
    }
    __syncthreads();

    // epilogue: warp per row, lane = 4 cols, conflict-free
    for (int rr = wid; rr < 64; rr += 16){
        int grow = m0 + rr;
        if (grow >= NN) continue;
        int col = lane*4;
        float4 r4 = *(float4*)(sGr + rr*128 + col);
        float4 z4 = *(float4*)(sGz + rr*128 + col);
        float4 i4 = *(float4*)(sGi + rr*128 + col);
        float4 n4 = *(float4*)(sGn + rr*128 + col);
        float4 h4 = *(float4*)(sHval + rr*128 + col);
        float4 br = *(float4*)(sbias + col);
        float4 bz = *(float4*)(sbias + 128 + col);
        float4 bi = *(float4*)(sbias + 256 + col);
        float4 bh = *(float4*)(sbias + 384 + col);
        float4 o;
        {
            float r_ = sigm(r4.x + br.x), z_ = sigm(z4.x + bz.x);
            float n_ = tanhf(i4.x + bi.x + r_*(n4.x + bh.x));
            o.x = (1.f - z_)*n_ + z_*h4.x;
        }
        {
            float r_ = sigm(r4.y + br.y), z_ = sigm(z4.y + bz.y);
            float n_ = tanhf(i4.y + bi.y + r_*(n4.y + bh.y));
            o.y = (1.f - z_)*n_ + z_*h4.y;
        }
        {
            float r_ = sigm(r4.z + br.z), z_ = sigm(z4.z + bz.z);
            float n_ = tanhf(i4.z + bi.z + r_*(n4.z + bh.z));
            o.z = (1.f - z_)*n_ + z_*h4.z;
        }
        {
            float r_ = sigm(r4.w + br.w), z_ = sigm(z4.w + bz.w);
            float n_ = tanhf(i4.w + bi.w + r_*(n4.w + bh.w));
            o.w = (1.f - z_)*n_ + z_*h4.w;
        }
        *(float4*)(Hout + (size_t)grow*HH + col) = o;
    }
}

// ---------------- LN + GELU after projection (warp per row) ----------------
__global__ void ln_gelu(const float* __restrict__ lnw, const float* __restrict__ lnb){
    int gw = (blockIdx.x*blockDim.x + threadIdx.x) >> 5;
    if (gw >= NN) return;
    int lane = threadIdx.x & 31;
    float xv[4], s = 0.f, s2 = 0.f;
    #pragma unroll
    for (int i = 0; i < 4; i++){
        xv[i] = g_proj[(size_t)gw*HH + lane + 32*i];
        s += xv[i]; s2 += xv[i]*xv[i];
    }
    #pragma unroll
    for (int o = 16; o; o >>= 1){
        s  += __shfl_xor_sync(0xffffffffu, s,  o);
        s2 += __shfl_xor_sync(0xffffffffu, s2, o);
    }
    float mu = s*(1.f/HH), var = s2*(1.f/HH) - mu*mu;
    float rstd = rsqrtf(var + 1e-5f);
    #pragma unroll
    for (int i = 0; i < 4; i++){
        int j = lane + 32*i;
        float y = (xv[i] - mu)*rstd*lnw[j] + lnb[j];
        g_h0[(size_t)gw*HH + j] = 0.5f*y*(1.f + erff(y*0.7071067811865476f));
    }
}

// ---------------- fused: per-view LN + residual + attention softmax/combine ----------
__global__ void ln_attn(const float* __restrict__ hall,
                        const float* __restrict__ vlnw, const float* __restrict__ vlnb){
    int gw = (blockIdx.x*blockDim.x + threadIdx.x) >> 5;
    if (gw >= NN) return;
    int lane = threadIdx.x & 31;
    float h0v[4], qkv[4];
    #pragma unroll
    for (int i = 0; i < 4; i++){
        h0v[i] = g_h0[(size_t)gw*HH + lane + 32*i];
        qkv[i] = g_qk[(size_t)gw*HH + lane + 32*i];
    }
    float y[4][4], sc[4];
    #pragma unroll
    for (int v = 0; v < 4; v++){
        float xv[4], s = 0.f, s2 = 0.f;
        #pragma unroll
        for (int i = 0; i < 4; i++){
            xv[i] = hall[((size_t)v*NN + gw)*HH + lane + 32*i];
            s += xv[i]; s2 += xv[i]*xv[i];
        }
        #pragma unroll
        for (int o = 16; o; o >>= 1){
            s  += __shfl_xor_sync(0xffffffffu, s,  o);
            s2 += __shfl_xor_sync(0xffffffffu, s2, o);
        }
        float mu = s*(1.f/HH), var = s2*(1.f/HH) - mu*mu;
        float rstd = rsqrtf(var + 1e-5f);
        float p = 0.f;
        #pragma unroll
        for (int i = 0; i < 4; i++){
            int j = lane + 32*i;
            y[v][i] = (xv[i] - mu)*rstd*vlnw[v*HH + j] + vlnb[v*HH + j] + h0v[i];
            p += qkv[i]*y[v][i];
        }
        #pragma unroll
        for (int o = 16; o; o >>= 1) p += __shfl_xor_sync(0xffffffffu, p, o);
        sc[v] = p * 0.08838834764831845f;
    }
    float mx = fmaxf(fmaxf(sc[0], sc[1]), fmaxf(sc[2], sc[3]));
    float ex[4], sum = 0.f;
    #pragma unroll
    for (int v = 0; v < 4; v++){ ex[v] = expf(sc[v] - mx); sum += ex[v]; }
    float inv = 1.f/sum;
    #pragma unroll
    for (int i = 0; i < 4; i++){
        float o = 0.f;
        #pragma unroll
        for (int v = 0; v < 4; v++) o += ex[v]*inv*y[v][i];
        g_fused[(size_t)gw*HH + lane + 32*i] = o;
    }
}

// ---------------- pooling ----------------
__global__ void pool_init(){
    int i = blockIdx.x*blockDim.x + threadIdx.x;
    if (i < BB*HH){ g_psum[i] = 0.f; g_pmax[i] = 0u; }
    if (i < BB) g_cnt[i] = 0.f;
}
__global__ void pool_acc(const int* __restrict__ batch){
    int j = threadIdx.x;
    int n0 = blockIdx.x * 64;
    int cur = -1; float sum = 0.f, mx = -1e30f; int cnt = 0;
    for (int t = 0; t < 64; t++){
        int n = n0 + t;
        if (n >= NN) break;
        int b = batch[n];
        if (b != cur){
            if (cur >= 0){
                atomicAdd(&g_psum[cur*HH + j], sum);
                atomicMax(&g_pmax[cur*HH + j], fenc(mx));
                if (j == 0) atomicAdd(&g_cnt[cur], (float)cnt);
            }
            cur = b; sum = 0.f; mx = -1e30f; cnt = 0;
        }
        float f = g_fused[(size_t)n*HH + j];
        sum += f; mx = fmaxf(mx, f); cnt++;
    }
    if (cur >= 0){
        atomicAdd(&g_psum[cur*HH + j], sum);
        atomicMax(&g_pmax[cur*HH + j], fenc(mx));
        if (j == 0) atomicAdd(&g_cnt[cur], (float)cnt);
    }
}

// ---------------- classifier MLP ----------------
__global__ void classifier(const float* __restrict__ c1w, const float* __restrict__ c1b,
                           const float* __restrict__ c2w, const float* __restrict__ c2b,
                           const float* __restrict__ c3w, const float* __restrict__ c3b,
                           float* __restrict__ out){
    __shared__ float gsh[2*HH], h1[HH], h2[64];
    int b = blockIdx.x, j = threadIdx.x;
    float cnt = fmaxf(g_cnt[b], 1.f);
    gsh[j]      = g_psum[b*HH + j] / cnt;
    gsh[HH + j] = fdec(g_pmax[b*HH + j]);
    __syncthreads();
    float a = c1b[j];
    for (int k = 0; k < 2*HH; k++) a += gsh[k]*c1w[k*HH + j];
    h1[j] = fmaxf(a, 0.f);
    __syncthreads();
    if (j < 64){
        float a2 = c2b[j];
        for (int k = 0; k < HH; k++) a2 += h1[k]*c2w[k*64 + j];
        h2[j] = fmaxf(a2, 0.f);
    }
    __syncthreads();
    if (j == 0){
        float o = c3b[0];
        for (int k = 0; k < 64; k++) o += h2[k]*c3w[k];
        out[b] = o;
    }
}

// ---------------- launch ----------------
extern "C" void kernel_launch(void* const* d_in, const int* in_sizes, int n_in,
                              void* d_out, int out_size){
    (void)in_sizes; (void)n_in; (void)out_size;
    const float* x      = (const float*)d_in[0];
    const int*   ei     = (const int*)  d_in[1];
    const int*   et     = (const int*)  d_in[2];
    const int*   batch  = (const int*)  d_in[3];
    const float* proj_w = (const float*)d_in[4];
    const float* proj_b = (const float*)d_in[5];
    const float* ln0w   = (const float*)d_in[6];
    const float* ln0b   = (const float*)d_in[7];
    const float* ggnn   = (const float*)d_in[8];
    const float* wih    = (const float*)d_in[9];
    const float* whh    = (const float*)d_in[10];
    const float* bih    = (const float*)d_in[11];
    const float* bhh    = (const float*)d_in[12];
    const float* vlnw   = (const float*)d_in[13];
    const float* vlnb   = (const float*)d_in[14];
    const float* qw     = (const float*)d_in[15];
    const float* qb     = (const float*)d_in[16];
    const float* kw     = (const float*)d_in[17];
    /* kb = d_in[18] unused: q.kb is constant across views -> softmax-invariant */
    const float* c1w    = (const float*)d_in[19];
    const float* c1b    = (const float*)d_in[20];
    const float* c2w    = (const float*)d_in[21];
    const float* c2b    = (const float*)d_in[22];
    const float* c3w    = (const float*)d_in[23];
    const float* c3b    = (const float*)d_in[24];
    float* out = (float*)d_out;

    float *p_h0, *p_hallA, *p_hallB, *p_proj, *p_q, *p_qk;
    uint4 *p_frag, *p_fragW;
    int* p_rowptr;
    cudaGetSymbolAddress((void**)&p_h0,    g_h0);
    cudaGetSymbolAddress((void**)&p_hallA, g_hallA);
    cudaGetSymbolAddress((void**)&p_hallB, g_hallB);
    cudaGetSymbolAddress((void**)&p_proj,  g_proj);
    cudaGetSymbolAddress((void**)&p_q,     g_q);
    cudaGetSymbolAddress((void**)&p_qk,    g_qk);
    cudaGetSymbolAddress((void**)&p_frag,  g_frag);
    cudaGetSymbolAddress((void**)&p_fragW, g_fragW);
    cudaGetSymbolAddress((void**)&p_rowptr, g_rowptr);

    const int GRU_SMEM = 133120 + 32768;   // 165888
    cudaFuncSetAttribute(gru_fused, cudaFuncAttributeMaxDynamicSharedMemorySize, GRU_SMEM);
    const int WC_SMEM = (2*128*129 + 128*128) * 4;  // 197632
    cudaFuncSetAttribute(wcomb_prep, cudaFuncAttributeMaxDynamicSharedMemorySize, WC_SMEM);

    const size_t NH = (size_t)NN*HH;

    // CSR build (per launch)
    csr_zero<<<(SEGN + 255)/256, 256>>>();
    csr_count<<<(EE + 255)/256, 256>>>(ei, et);
    csr_scan1<<<SCAN_BLKS, 1024>>>();
    csr_scan2<<<1, 1024>>>();
    csr_scan3<<<(SEGN + 255)/256, 256>>>();
    csr_fill<<<(EE + 255)/256, 256>>>(ei, et);

    prep_frags<<<(FRAG_TOTAL + 255)/256, 256>>>(whh, proj_w, qw, kw);
    wcomb_prep<<<dim3(16,3), 256, WC_SMEM>>>(ggnn, wih);

    // input projection: g_proj = x @ proj_w + proj_b ; then LN+GELU -> g_h0
    gemm_mma<<<dim3(MT,1), 256>>>(x, INF_, NN, p_frag + OFF_PROJ, 16, 32, proj_b, p_proj, HH, 0);
    ln_gelu<<<(NN*32 + 255)/256, 256>>>(ln0w, ln0b);

    // q = tanh(h0 @ qw + qb), qk = q @ kw^T
    gemm_mma<<<dim3(MT,1), 256>>>(p_h0, HH, NN, p_frag + OFF_QW, 16, 8, qb, p_q, HH, 1);
    gemm_mma<<<dim3(MT,1), 256>>>(p_q, HH, NN, p_frag + OFF_KWT, 16, 8, nullptr, p_qk, HH, 0);

    // ping-pong: h0 -> A -> B -> A -> B
    float* bufs[2] = { p_hallA, p_hallB };
    const float* hin = p_h0;
    size_t hinStride = 0;
    float* hout = p_hallA;
    for (int i = 0; i < 4; i++){
        gru_fused<<<4*GRU_GRID, 512, GRU_SMEM>>>(hin, hout,
            p_fragW + (size_t)i*12288, p_frag + OFF_WHH,
            bih, bhh, p_rowptr, hinStride);
        hin = hout;
        hinStride = NH;
        hout = bufs[(i + 1) & 1];
    }
    const float* hfinal = hin;

    // fused per-view LN + residual + attention combine
    ln_attn<<<(NN*32 + 255)/256, 256>>>(hfinal, vlnw, vlnb);

    pool_init<<<(BB*HH + 255)/256, 256>>>();
    pool_acc<<<(NN + 63)/64, 128>>>(batch);
    classifier<<<BB, 128>>>(c1w, c1b, c2w, c2b, c3w, c3b, out);
}

// round 13
// speedup vs baseline: 1.1171x; 1.1171x over previous
#include <cuda_runtime.h>
#include <cuda_bf16.h>
#include <cstdint>
#include <math.h>

#define NN   50000
#define EE   600000
#define INF_ 512
#define HH   128
#define H3   384
#define BB   64
#define MT   ((NN + 127) / 128)      // 391
#define SEGN (4*NN)
#define SCAN_BLKS ((SEGN + 1023)/1024)
#define GRU_GRID ((NN + 31)/32)      // 1563 (32-row tiles)

// ---------------- device scratch ----------------
__device__ float g_h0   [(size_t)NN*HH];
__device__ float g_hallA[(size_t)4*NN*HH];
__device__ float g_hallB[(size_t)4*NN*HH];
__device__ float g_proj [(size_t)NN*HH];
__device__ float g_q    [(size_t)NN*HH];
__device__ float g_qk   [(size_t)NN*HH];
__device__ float g_fused[(size_t)NN*HH];
__device__ float g_psum[BB*HH];
__device__ unsigned g_pmax[BB*HH];
__device__ float g_cnt [BB];

__device__ int g_deg   [SEGN];
__device__ int g_scanT [SEGN];
__device__ int g_part  [SCAN_BLKS];
__device__ int g_partS [SCAN_BLKS];
__device__ int g_rowptr[SEGN + 1];
__device__ int g_woff  [SEGN];
__device__ int g_csrsrc[EE];

#define OFF_WHH  0
#define OFF_PROJ 49152
#define OFF_QW   65536
#define OFF_KWT  69632
#define FRAG_TOTAL 73728
__device__ uint4 g_frag[FRAG_TOTAL];
__device__ uint4 g_fragW[16u*12288u];

__constant__ int c_v_of_t[13] = {0,1,1,1,2,2,2,3,3,0,0,3,3};

// ---------------- helpers ----------------
__device__ __forceinline__ uint32_t packbf(float a, float b){
    __nv_bfloat162 t = __halves2bfloat162(__float2bfloat16(a), __float2bfloat16(b));
    return *reinterpret_cast<uint32_t*>(&t);
}
__device__ __forceinline__ uint2 packhl(float2 v){
    float hx = __bfloat162float(__float2bfloat16(v.x));
    float hy = __bfloat162float(__float2bfloat16(v.y));
    return make_uint2(packbf(v.x, v.y), packbf(v.x - hx, v.y - hy));
}
__device__ __forceinline__ unsigned fenc(float f){
    unsigned b = __float_as_uint(f);
    return (b & 0x80000000u) ? ~b : (b | 0x80000000u);
}
__device__ __forceinline__ float fdec(unsigned u){
    return __uint_as_float((u & 0x80000000u) ? (u & 0x7fffffffu) : ~u);
}
__device__ __forceinline__ float sigm(float x){ return 1.f/(1.f + expf(-x)); }

#define MMA16816(d, a, b0_, b1_) \
  asm volatile("mma.sync.aligned.m16n8k16.row.col.f32.bf16.bf16.f32 " \
    "{%0,%1,%2,%3}, {%4,%5,%6,%7}, {%8,%9}, {%0,%1,%2,%3};" \
    : "+f"((d)[0]), "+f"((d)[1]), "+f"((d)[2]), "+f"((d)[3]) \
    : "r"((a)[0]), "r"((a)[1]), "r"((a)[2]), "r"((a)[3]), "r"(b0_), "r"(b1_))

// ---------------- CSR build ----------------
__global__ void csr_zero(){
    int i = blockIdx.x*blockDim.x + threadIdx.x;
    if (i < SEGN) g_deg[i] = 0;
}
__global__ void csr_count(const int* __restrict__ ei, const int* __restrict__ et){
    int e = blockIdx.x*blockDim.x + threadIdx.x;
    if (e >= EE) return;
    int v = c_v_of_t[et[e]];
    atomicAdd(&g_deg[v*NN + ei[EE + e]], 1);
}
__global__ void csr_scan1(){
    __shared__ int sm[1024];
    int t = threadIdx.x, b = blockIdx.x;
    int i = b*1024 + t;
    int v = (i < SEGN) ? g_deg[i] : 0;
    sm[t] = v;
    __syncthreads();
    #pragma unroll
    for (int o = 1; o < 1024; o <<= 1){
        int add = (t >= o) ? sm[t - o] : 0;
        __syncthreads();
        sm[t] += add;
        __syncthreads();
    }
    if (i < SEGN) g_scanT[i] = sm[t];
    if (t == 1023) g_part[b] = sm[1023];
}
__global__ void csr_scan2(){
    __shared__ int sm[SCAN_BLKS];
    int t = threadIdx.x;
    if (t < SCAN_BLKS) sm[t] = g_part[t];
    __syncthreads();
    if (t == 0){
        int run = 0;
        for (int i = 0; i < SCAN_BLKS; i++){ run += sm[i]; g_partS[i] = run; }
    }
}
__global__ void csr_scan3(){
    int i = blockIdx.x*blockDim.x + threadIdx.x;
    if (i >= SEGN) return;
    int b = i >> 10;
    int base = (b > 0) ? g_partS[b-1] : 0;
    int excl = base + g_scanT[i] - g_deg[i];
    g_rowptr[i] = excl;
    g_woff[i]   = excl;
    if (i == 0) g_rowptr[SEGN] = EE;
}
__global__ void csr_fill(const int* __restrict__ ei, const int* __restrict__ et){
    int e = blockIdx.x*blockDim.x + threadIdx.x;
    if (e >= EE) return;
    int v = c_v_of_t[et[e]];
    int pos = atomicAdd(&g_woff[v*NN + ei[EE + e]], 1);
    g_csrsrc[pos] = ei[e];
}

// ---------------- prep: whh/proj/qw/kw^T -> bf16 hi/lo fragment images ----------------
__global__ void prep_frags(const float* __restrict__ whh, const float* __restrict__ projw,
                           const float* __restrict__ qw, const float* __restrict__ kw){
    int tid = blockIdx.x*blockDim.x + threadIdx.x;
    if (tid >= FRAG_TOTAL) return;
    const float* M; int NT, rel; bool tr;
    if (tid < OFF_PROJ){       int q = tid;        rel = q % 12288; M = whh + (size_t)(q/12288)*49152; NT = 48; tr = true; }
    else if (tid < OFF_QW){    rel = tid-OFF_PROJ; M = projw; NT = 16; tr = false; }
    else if (tid < OFF_KWT){   rel = tid-OFF_QW;   M = qw;    NT = 16; tr = false; }
    else{                      rel = tid-OFF_KWT;  M = kw;    NT = 16; tr = true; }
    int lane = rel & 31, t2 = rel >> 5;
    int nt = t2 % NT, kt = t2 / NT;
    int n = nt*8 + (lane >> 2), k0 = kt*16 + (lane & 3)*2;
    float v[4];
    #pragma unroll
    for (int q = 0; q < 4; q++){
        int k = k0 + (q >> 1)*8 + (q & 1);
        v[q] = tr ? M[(size_t)n*128 + k] : M[(size_t)k*128 + n];
    }
    float h[4], l[4];
    #pragma unroll
    for (int q = 0; q < 4; q++){
        h[q] = __bfloat162float(__float2bfloat16(v[q]));
        l[q] = v[q] - h[q];
    }
    uint4 o;
    o.x = packbf(h[0], h[1]); o.y = packbf(h[2], h[3]);
    o.z = packbf(l[0], l[1]); o.w = packbf(l[2], l[3]);
    g_frag[tid] = o;
}

// ---------------- Wcomb = ggnn[v,i] @ wih[v]^T -> fragment image ----------------
__global__ __launch_bounds__(256)
void wcomb_prep(const float* __restrict__ ggnn, const float* __restrict__ wih){
    extern __shared__ float s[];
    float* As = s;
    float* Ws = s + 128*129;
    float* Cs = s + 2*128*129;
    int vi = blockIdx.x, cblk = blockIdx.y, v = vi >> 2;
    const float* A = ggnn + (size_t)vi*16384;
    const float* W = wih + ((size_t)v*H3 + cblk*128)*128;
    int tid = threadIdx.x;
    for (int i = tid; i < 16384; i += 256){
        int r = i >> 7, j = i & 127;
        As[j*129 + r] = A[i];
        Ws[j*129 + r] = W[i];
    }
    __syncthreads();
    int tx = tid & 15, ty = tid >> 4;
    float acc[8][8];
    #pragma unroll
    for (int a = 0; a < 8; a++)
        #pragma unroll
        for (int b = 0; b < 8; b++) acc[a][b] = 0.f;
    for (int j = 0; j < 128; j++){
        float av[8], wv[8];
        #pragma unroll
        for (int q = 0; q < 8; q++){
            av[q] = As[j*129 + ty*8 + q];
            wv[q] = Ws[j*129 + tx*8 + q];
        }
        #pragma unroll
        for (int a = 0; a < 8; a++)
            #pragma unroll
            for (int b = 0; b < 8; b++) acc[a][b] += av[a]*wv[b];
    }
    #pragma unroll
    for (int a = 0; a < 8; a++)
        #pragma unroll
        for (int b = 0; b < 8; b++)
            Cs[(ty*8+a)*128 + tx*8+b] = acc[a][b];
    __syncthreads();
    uint4* dst = g_fragW + (size_t)vi*12288;
    for (int it = tid; it < 4096; it += 256){
        int lane = it & 31, t2 = it >> 5;
        int lnt = t2 & 15, kt = t2 >> 4;
        int c = lnt*8 + (lane >> 2);
        int k0 = kt*16 + (lane & 3)*2;
        float vq[4], h[4], l[4];
        #pragma unroll
        for (int q = 0; q < 4; q++){
            int k = k0 + (q >> 1)*8 + (q & 1);
            vq[q] = Cs[k*128 + c];
            h[q] = __bfloat162float(__float2bfloat16(vq[q]));
            l[q] = vq[q] - h[q];
        }
        uint4 o;
        o.x = packbf(h[0], h[1]); o.y = packbf(h[2], h[3]);
        o.z = packbf(l[0], l[1]); o.w = packbf(l[2], l[3]);
        int ntg = cblk*16 + lnt;
        dst[((size_t)(kt*48 + ntg))*32 + lane] = o;
    }
}

// ---------------- HMMA GEMM (proj / q / qk) ----------------
__global__ __launch_bounds__(256)
void gemm_mma(const float* __restrict__ A, int lda, int M,
              const uint4* __restrict__ frag, int NT, int KT,
              const float* __restrict__ bias, float* __restrict__ C,
              int ldc, int act){
    int tid = threadIdx.x, wid = tid >> 5, lane = tid & 31;
    int wm = wid >> 1, wn = wid & 1;
    int gid = lane >> 2, tig = lane & 3;
    int rowBase = blockIdx.x*128 + wm*32 + gid;
    int ntG0 = blockIdx.y*16 + wn*8;

    float acc[2][8][4];
    #pragma unroll
    for (int mt = 0; mt < 2; mt++)
        #pragma unroll
        for (int nt = 0; nt < 8; nt++)
            #pragma unroll
            for (int q = 0; q < 4; q++) acc[mt][nt][q] = 0.f;

    float2 ax[2][4];
    auto loadA = [&](int kt){
        #pragma unroll
        for (int mt = 0; mt < 2; mt++){
            int r = rowBase + mt*16;
            int k = kt*16 + tig*2;
            bool p0 = (r < M), p1 = (r + 8 < M);
            const float* base0 = A + (size_t)r*lda + k;
            const float* base1 = A + (size_t)(r+8)*lda + k;
            ax[mt][0] = p0 ? *(const float2*)(base0)     : make_float2(0.f, 0.f);
            ax[mt][1] = p1 ? *(const float2*)(base1)     : make_float2(0.f, 0.f);
            ax[mt][2] = p0 ? *(const float2*)(base0 + 8) : make_float2(0.f, 0.f);
            ax[mt][3] = p1 ? *(const float2*)(base1 + 8) : make_float2(0.f, 0.f);
        }
    };
    loadA(0);
    uint4 bcur = frag[((size_t)(0*NT + ntG0))*32 + lane];

    for (int kt = 0; kt < KT; kt++){
        uint32_t Ah[2][4], Al[2][4];
        #pragma unroll
        for (int mt = 0; mt < 2; mt++){
            #pragma unroll
            for (int q = 0; q < 4; q++){
                float2 vv = ax[mt][q];
                float hx = __bfloat162float(__float2bfloat16(vv.x));
                float hy = __bfloat162float(__float2bfloat16(vv.y));
                Ah[mt][q] = packbf(vv.x, vv.y);
                Al[mt][q] = packbf(vv.x - hx, vv.y - hy);
            }
        }
        if (kt + 1 < KT) loadA(kt + 1);
        #pragma unroll
        for (int nt = 0; nt < 8; nt++){
            uint4 bn;
            if (nt < 7)           bn = frag[((size_t)(kt*NT + ntG0 + nt + 1))*32 + lane];
            else if (kt + 1 < KT) bn = frag[((size_t)((kt+1)*NT + ntG0))*32 + lane];
            else                  bn = bcur;
            #pragma unroll
            for (int mt = 0; mt < 2; mt++){
                MMA16816(acc[mt][nt], Ah[mt], bcur.x, bcur.y);
                MMA16816(acc[mt][nt], Ah[mt], bcur.z, bcur.w);
                MMA16816(acc[mt][nt], Al[mt], bcur.x, bcur.y);
            }
            bcur = bn;
        }
    }

    #pragma unroll
    for (int nt = 0; nt < 8; nt++){
        int col = (ntG0 + nt)*8 + tig*2;
        float b0 = 0.f, b1 = 0.f;
        if (bias){ b0 = bias[col]; b1 = bias[col + 1]; }
        #pragma unroll
        for (int mt = 0; mt < 2; mt++){
            int r = rowBase + mt*16;
            float v0 = acc[mt][nt][0] + b0, v1 = acc[mt][nt][1] + b1;
            float v2 = acc[mt][nt][2] + b0, v3 = acc[mt][nt][3] + b1;
            if (act == 1){ v0 = tanhf(v0); v1 = tanhf(v1); v2 = tanhf(v2); v3 = tanhf(v3); }
            if (r < M)     *(float2*)(C + (size_t)r*ldc + col)     = make_float2(v0, v1);
            if (r + 8 < M) *(float2*)(C + (size_t)(r+8)*ldc + col) = make_float2(v2, v3);
        }
    }
}

// ---------------- fused GRU cell v4: 32-row tiles, 256 thr, 2 CTAs/SM ----------------
// 8 warps = 4 gates x 2 col-slices (64 cols each, 8 nt).
#define GPASS(SA, FP, GATE, ACC) \
  _Pragma("unroll 1") \
  for (int kt = 0; kt < 8; kt++){ \
    _Pragma("unroll") \
    for (int nt = 0; nt < 8; nt++){ \
      uint4 b = (FP)[((size_t)(kt*48 + (GATE)*16 + sub*8 + nt))*32 + lane]; \
      _Pragma("unroll") \
      for (int mt = 0; mt < 2; mt++){ \
        uint4 fh = (SA)[(mt*8 + kt)*32 + lane]; \
        uint4 fl = (SA)[512 + (mt*8 + kt)*32 + lane]; \
        uint32_t AH_[4] = {fh.x, fh.y, fh.z, fh.w}; \
        uint32_t AL_[4] = {fl.x, fl.y, fl.z, fl.w}; \
        MMA16816(ACC[mt][nt], AH_, b.x, b.y); \
        MMA16816(ACC[mt][nt], AH_, b.z, b.w); \
        MMA16816(ACC[mt][nt], AL_, b.x, b.y); \
      } \
    } \
  }

__global__ __launch_bounds__(256, 2)
void gru_fused(const float* __restrict__ Hin, float* __restrict__ Hout,
               const uint4* __restrict__ wcF, const uint4* __restrict__ whhF,
               const float* __restrict__ bih, const float* __restrict__ bhh,
               const int* __restrict__ rowptrB, size_t hinStride){
    extern __shared__ char sm[];
    uint4* sAg   = (uint4*)sm;             // 1024 uint4 (16KB) | post-MMA: gate r
    uint4* sH    = (uint4*)(sm + 16384);   // 16KB             | post-MMA: gate z
    float* sHval = (float*)(sm + 32768);   // 32*128 fp32 (16KB), live to end
    float* sAval = (float*)(sm + 49152);   // 16KB             | post-MMA: gate inn
    float* sbias = (float*)(sm + 65536);   // 512 f (2KB)
    float* sGn   = (float*)(sm + 67584);   // 16KB gate hn
    float* sGr   = (float*)sm;
    float* sGz   = (float*)(sm + 16384);
    float* sGi   = sAval;
    int tid = threadIdx.x, wid = tid >> 5, lane = tid & 31;
    int gid = lane >> 2, tig = lane & 3;

    int v   = blockIdx.x / GRU_GRID;
    int blk = blockIdx.x % GRU_GRID;
    int m0 = blk*32;
    const float* Hsrc = Hin + (size_t)v * hinStride;
    Hout   += (size_t)v * NN * HH;
    wcF    += (size_t)v * 49152;
    whhF   += (size_t)v * 12288;
    bih    += v * H3;
    bhh    += v * H3;
    const int* rowptr = rowptrB + v * NN;

    if (tid < 128){
        sbias[tid]     = bih[tid]     + bhh[tid];
        sbias[128+tid] = bih[128+tid] + bhh[128+tid];
        sbias[256+tid] = bih[256+tid];
        sbias[384+tid] = bhh[256+tid];
    }
    // h tile (32 rows)
    for (int it = tid; it < 32*32; it += 256){
        int r = it >> 5, c4 = it & 31;
        float4 hv = make_float4(0.f,0.f,0.f,0.f);
        if (m0 + r < NN) hv = *(const float4*)(Hsrc + (size_t)(m0+r)*HH + c4*4);
        *(float4*)(sHval + r*128 + c4*4) = hv;
    }
    // CSR gather (4 rows per warp)
    for (int rr = wid; rr < 32; rr += 8){
        int grow = m0 + rr;
        float4 acc = make_float4(0.f,0.f,0.f,0.f);
        if (grow < NN){
            int s = rowptr[grow], e = rowptr[grow + 1];
            int idx = s;
            while (idx + 4 <= e){
                int a0 = g_csrsrc[idx], a1 = g_csrsrc[idx+1];
                int a2 = g_csrsrc[idx+2], a3 = g_csrsrc[idx+3];
                float4 v0 = *(const float4*)(Hsrc + (size_t)a0*HH + lane*4);
                float4 v1 = *(const float4*)(Hsrc + (size_t)a1*HH + lane*4);
                float4 v2 = *(const float4*)(Hsrc + (size_t)a2*HH + lane*4);
                float4 v3 = *(const float4*)(Hsrc + (size_t)a3*HH + lane*4);
                acc.x += v0.x + v1.x + v2.x + v3.x;
                acc.y += v0.y + v1.y + v2.y + v3.y;
                acc.z += v0.z + v1.z + v2.z + v3.z;
                acc.w += v0.w + v1.w + v2.w + v3.w;
                idx += 4;
            }
            while (idx < e){
                int a0 = g_csrsrc[idx];
                float4 v0 = *(const float4*)(Hsrc + (size_t)a0*HH + lane*4);
                acc.x += v0.x; acc.y += v0.y; acc.z += v0.z; acc.w += v0.w;
                idx++;
            }
        }
        *(float4*)(sAval + rr*128 + lane*4) = acc;
    }
    __syncthreads();
    // pack G + h into bf16 hi/lo fragments (2 mt x 8 kt x 32 lanes = 512 items)
    for (int it = tid; it < 512; it += 256){
        int mt = it >> 8, kt = (it >> 5) & 7, ln = it & 31;
        int g = ln >> 2, tg = ln & 3;
        int r0 = mt*16 + g, r1 = r0 + 8;
        int k = kt*16 + tg*2;
        float2 a00 = *(const float2*)(sAval + r0*128 + k);
        float2 a01 = *(const float2*)(sAval + r0*128 + k + 8);
        float2 a10 = *(const float2*)(sAval + r1*128 + k);
        float2 a11 = *(const float2*)(sAval + r1*128 + k + 8);
        uint2 p0 = packhl(a00), p1 = packhl(a10), p2 = packhl(a01), p3 = packhl(a11);
        sAg[(mt*8 + kt)*32 + ln]       = make_uint4(p0.x, p1.x, p2.x, p3.x);
        sAg[512 + (mt*8 + kt)*32 + ln] = make_uint4(p0.y, p1.y, p2.y, p3.y);
        float2 h00 = *(const float2*)(sHval + r0*128 + k);
        float2 h01 = *(const float2*)(sHval + r0*128 + k + 8);
        float2 h10 = *(const float2*)(sHval + r1*128 + k);
        float2 h11 = *(const float2*)(sHval + r1*128 + k + 8);
        uint2 q0 = packhl(h00), q1 = packhl(h10), q2 = packhl(h01), q3 = packhl(h11);
        sH[(mt*8 + kt)*32 + ln]       = make_uint4(q0.x, q1.x, q2.x, q3.x);
        sH[512 + (mt*8 + kt)*32 + ln] = make_uint4(q0.y, q1.y, q2.y, q3.y);
    }
    __syncthreads();

    // MMA phase: warp = (gate g, col slice sub of 64 cols)
    int g = wid >> 1, sub = wid & 1;
    float acc[2][8][4];
    #pragma unroll
    for (int mt = 0; mt < 2; mt++)
        #pragma unroll
        for (int nt = 0; nt < 8; nt++)
            #pragma unroll
            for (int q = 0; q < 4; q++) acc[mt][nt][q] = 0.f;

    if (g == 0){ GPASS(sAg, wcF, 0, acc); GPASS(sH, whhF, 0, acc); }
    else if (g == 1){ GPASS(sAg, wcF, 1, acc); GPASS(sH, whhF, 1, acc); }
    else if (g == 2){ GPASS(sAg, wcF, 2, acc); }
    else            { GPASS(sH, whhF, 2, acc); }

    __syncthreads();

    // dump gate accumulators [32][128] per gate
    {
        float* gout = (g == 0) ? sGr : (g == 1) ? sGz : (g == 2) ? sGi : sGn;
        #pragma unroll
        for (int mt = 0; mt < 2; mt++){
            #pragma unroll
            for (int nt = 0; nt < 8; nt++){
                int col = sub*64 + nt*8 + tig*2;
                int r0 = mt*16 + gid;
                *(float2*)(gout + r0*128 + col)     = make_float2(acc[mt][nt][0], acc[mt][nt][1]);
                *(float2*)(gout + (r0+8)*128 + col) = make_float2(acc[mt][nt][2], acc[mt][nt][3]);
            }
        }
    }
    __syncthreads();

    // epilogue: warp per row (4 rows/warp), lane = 4 cols
    for (int rr = wid; rr < 32; rr += 8){
        int grow = m0 + rr;
        if (grow >= NN) continue;
        int col = lane*4;
        float4 r4 = *(float4*)(sGr + rr*128 + col);
        float4 z4 = *(float4*)(sGz + rr*128 + col);
        float4 i4 = *(float4*)(sGi + rr*128 + col);
        float4 n4 = *(float4*)(sGn + rr*128 + col);
        float4 h4 = *(float4*)(sHval + rr*128 + col);
        float4 br = *(float4*)(sbias + col);
        float4 bz = *(float4*)(sbias + 128 + col);
        float4 bi = *(float4*)(sbias + 256 + col);
        float4 bh = *(float4*)(sbias + 384 + col);
        float4 o;
        {
            float r_ = sigm(r4.x + br.x), z_ = sigm(z4.x + bz.x);
            float n_ = tanhf(i4.x + bi.x + r_*(n4.x + bh.x));
            o.x = (1.f - z_)*n_ + z_*h4.x;
        }
        {
            float r_ = sigm(r4.y + br.y), z_ = sigm(z4.y + bz.y);
            float n_ = tanhf(i4.y + bi.y + r_*(n4.y + bh.y));
            o.y = (1.f - z_)*n_ + z_*h4.y;
        }
        {
            float r_ = sigm(r4.z + br.z), z_ = sigm(z4.z + bz.z);
            float n_ = tanhf(i4.z + bi.z + r_*(n4.z + bh.z));
            o.z = (1.f - z_)*n_ + z_*h4.z;
        }
        {
            float r_ = sigm(r4.w + br.w), z_ = sigm(z4.w + bz.w);
            float n_ = tanhf(i4.w + bi.w + r_*(n4.w + bh.w));
            o.w = (1.f - z_)*n_ + z_*h4.w;
        }
        *(float4*)(Hout + (size_t)grow*HH + col) = o;
    }
}

// ---------------- LN + GELU after projection (warp per row) ----------------
__global__ void ln_gelu(const float* __restrict__ lnw, const float* __restrict__ lnb){
    int gw = (blockIdx.x*blockDim.x + threadIdx.x) >> 5;
    if (gw >= NN) return;
    int lane = threadIdx.x & 31;
    float xv[4], s = 0.f, s2 = 0.f;
    #pragma unroll
    for (int i = 0; i < 4; i++){
        xv[i] = g_proj[(size_t)gw*HH + lane + 32*i];
        s += xv[i]; s2 += xv[i]*xv[i];
    }
    #pragma unroll
    for (int o = 16; o; o >>= 1){
        s  += __shfl_xor_sync(0xffffffffu, s,  o);
        s2 += __shfl_xor_sync(0xffffffffu, s2, o);
    }
    float mu = s*(1.f/HH), var = s2*(1.f/HH) - mu*mu;
    float rstd = rsqrtf(var + 1e-5f);
    #pragma unroll
    for (int i = 0; i < 4; i++){
        int j = lane + 32*i;
        float y = (xv[i] - mu)*rstd*lnw[j] + lnb[j];
        g_h0[(size_t)gw*HH + j] = 0.5f*y*(1.f + erff(y*0.7071067811865476f));
    }
}

// ---------------- fused: per-view LN + residual + attention ----------
__global__ void ln_attn(const float* __restrict__ hall,
                        const float* __restrict__ vlnw, const float* __restrict__ vlnb){
    int gw = (blockIdx.x*blockDim.x + threadIdx.x) >> 5;
    if (gw >= NN) return;
    int lane = threadIdx.x & 31;
    float h0v[4], qkv[4];
    #pragma unroll
    for (int i = 0; i < 4; i++){
        h0v[i] = g_h0[(size_t)gw*HH + lane + 32*i];
        qkv[i] = g_qk[(size_t)gw*HH + lane + 32*i];
    }
    float y[4][4], sc[4];
    #pragma unroll
    for (int v = 0; v < 4; v++){
        float xv[4], s = 0.f, s2 = 0.f;
        #pragma unroll
        for (int i = 0; i < 4; i++){
            xv[i] = hall[((size_t)v*NN + gw)*HH + lane + 32*i];
            s += xv[i]; s2 += xv[i]*xv[i];
        }
        #pragma unroll
        for (int o = 16; o; o >>= 1){
            s  += __shfl_xor_sync(0xffffffffu, s,  o);
            s2 += __shfl_xor_sync(0xffffffffu, s2, o);
        }
        float mu = s*(1.f/HH), var = s2*(1.f/HH) - mu*mu;
        float rstd = rsqrtf(var + 1e-5f);
        float p = 0.f;
        #pragma unroll
        for (int i = 0; i < 4; i++){
            int j = lane + 32*i;
            y[v][i] = (xv[i] - mu)*rstd*vlnw[v*HH + j] + vlnb[v*HH + j] + h0v[i];
            p += qkv[i]*y[v][i];
        }
        #pragma unroll
        for (int o = 16; o; o >>= 1) p += __shfl_xor_sync(0xffffffffu, p, o);
        sc[v] = p * 0.08838834764831845f;
    }
    float mx = fmaxf(fmaxf(sc[0], sc[1]), fmaxf(sc[2], sc[3]));
    float ex[4], sum = 0.f;
    #pragma unroll
    for (int v = 0; v < 4; v++){ ex[v] = expf(sc[v] - mx); sum += ex[v]; }
    float inv = 1.f/sum;
    #pragma unroll
    for (int i = 0; i < 4; i++){
        float o = 0.f;
        #pragma unroll
        for (int v = 0; v < 4; v++) o += ex[v]*inv*y[v][i];
        g_fused[(size_t)gw*HH + lane + 32*i] = o;
    }
}

// ---------------- pooling ----------------
__global__ void pool_init(){
    int i = blockIdx.x*blockDim.x + threadIdx.x;
    if (i < BB*HH){ g_psum[i] = 0.f; g_pmax[i] = 0u; }
    if (i < BB) g_cnt[i] = 0.f;
}
__global__ void pool_acc(const int* __restrict__ batch){
    int j = threadIdx.x;
    int n0 = blockIdx.x * 64;
    int cur = -1; float sum = 0.f, mx = -1e30f; int cnt = 0;
    for (int t = 0; t < 64; t++){
        int n = n0 + t;
        if (n >= NN) break;
        int b = batch[n];
        if (b != cur){
            if (cur >= 0){
                atomicAdd(&g_psum[cur*HH + j], sum);
                atomicMax(&g_pmax[cur*HH + j], fenc(mx));
                if (j == 0) atomicAdd(&g_cnt[cur], (float)cnt);
            }
            cur = b; sum = 0.f; mx = -1e30f; cnt = 0;
        }
        float f = g_fused[(size_t)n*HH + j];
        sum += f; mx = fmaxf(mx, f); cnt++;
    }
    if (cur >= 0){
        atomicAdd(&g_psum[cur*HH + j], sum);
        atomicMax(&g_pmax[cur*HH + j], fenc(mx));
        if (j == 0) atomicAdd(&g_cnt[cur], (float)cnt);
    }
}

// ---------------- classifier MLP ----------------
__global__ void classifier(const float* __restrict__ c1w, const float* __restrict__ c1b,
                           const float* __restrict__ c2w, const float* __restrict__ c2b,
                           const float* __restrict__ c3w, const float* __restrict__ c3b,
                           float* __restrict__ out){
    __shared__ float gsh[2*HH], h1[HH], h2[64];
    int b = blockIdx.x, j = threadIdx.x;
    float cnt = fmaxf(g_cnt[b], 1.f);
    gsh[j]      = g_psum[b*HH + j] / cnt;
    gsh[HH + j] = fdec(g_pmax[b*HH + j]);
    __syncthreads();
    float a = c1b[j];
    for (int k = 0; k < 2*HH; k++) a += gsh[k]*c1w[k*HH + j];
    h1[j] = fmaxf(a, 0.f);
    __syncthreads();
    if (j < 64){
        float a2 = c2b[j];
        for (int k = 0; k < HH; k++) a2 += h1[k]*c2w[k*64 + j];
        h2[j] = fmaxf(a2, 0.f);
    }
    __syncthreads();
    if (j == 0){
        float o = c3b[0];
        for (int k = 0; k < 64; k++) o += h2[k]*c3w[k];
        out[b] = o;
    }
}

// ---------------- launch ----------------
extern "C" void kernel_launch(void* const* d_in, const int* in_sizes, int n_in,
                              void* d_out, int out_size){
    (void)in_sizes; (void)n_in; (void)out_size;
    const float* x      = (const float*)d_in[0];
    const int*   ei     = (const int*)  d_in[1];
    const int*   et     = (const int*)  d_in[2];
    const int*   batch  = (const int*)  d_in[3];
    const float* proj_w = (const float*)d_in[4];
    const float* proj_b = (const float*)d_in[5];
    const float* ln0w   = (const float*)d_in[6];
    const float* ln0b   = (const float*)d_in[7];
    const float* ggnn   = (const float*)d_in[8];
    const float* wih    = (const float*)d_in[9];
    const float* whh    = (const float*)d_in[10];
    const float* bih    = (const float*)d_in[11];
    const float* bhh    = (const float*)d_in[12];
    const float* vlnw   = (const float*)d_in[13];
    const float* vlnb   = (const float*)d_in[14];
    const float* qw     = (const float*)d_in[15];
    const float* qb     = (const float*)d_in[16];
    const float* kw     = (const float*)d_in[17];
    /* kb unused: softmax-invariant */
    const float* c1w    = (const float*)d_in[19];
    const float* c1b    = (const float*)d_in[20];
    const float* c2w    = (const float*)d_in[21];
    const float* c2b    = (const float*)d_in[22];
    const float* c3w    = (const float*)d_in[23];
    const float* c3b    = (const float*)d_in[24];
    float* out = (float*)d_out;

    float *p_h0, *p_hallA, *p_hallB, *p_proj, *p_q, *p_qk;
    uint4 *p_frag, *p_fragW;
    int* p_rowptr;
    cudaGetSymbolAddress((void**)&p_h0,    g_h0);
    cudaGetSymbolAddress((void**)&p_hallA, g_hallA);
    cudaGetSymbolAddress((void**)&p_hallB, g_hallB);
    cudaGetSymbolAddress((void**)&p_proj,  g_proj);
    cudaGetSymbolAddress((void**)&p_q,     g_q);
    cudaGetSymbolAddress((void**)&p_qk,    g_qk);
    cudaGetSymbolAddress((void**)&p_frag,  g_frag);
    cudaGetSymbolAddress((void**)&p_fragW, g_fragW);
    cudaGetSymbolAddress((void**)&p_rowptr, g_rowptr);

    const int GRU_SMEM = 83968;   // 82KB -> 2 CTAs/SM
    cudaFuncSetAttribute(gru_fused, cudaFuncAttributeMaxDynamicSharedMemorySize, GRU_SMEM);
    const int WC_SMEM = (2*128*129 + 128*128) * 4;
    cudaFuncSetAttribute(wcomb_prep, cudaFuncAttributeMaxDynamicSharedMemorySize, WC_SMEM);

    const size_t NH = (size_t)NN*HH;

    csr_zero<<<(SEGN + 255)/256, 256>>>();
    csr_count<<<(EE + 255)/256, 256>>>(ei, et);
    csr_scan1<<<SCAN_BLKS, 1024>>>();
    csr_scan2<<<1, 1024>>>();
    csr_scan3<<<(SEGN + 255)/256, 256>>>();
    csr_fill<<<(EE + 255)/256, 256>>>(ei, et);

    prep_frags<<<(FRAG_TOTAL + 255)/256, 256>>>(whh, proj_w, qw, kw);
    wcomb_prep<<<dim3(16,3), 256, WC_SMEM>>>(ggnn, wih);

    gemm_mma<<<dim3(MT,1), 256>>>(x, INF_, NN, p_frag + OFF_PROJ, 16, 32, proj_b, p_proj, HH, 0);
    ln_gelu<<<(NN*32 + 255)/256, 256>>>(ln0w, ln0b);

    gemm_mma<<<dim3(MT,1), 256>>>(p_h0, HH, NN, p_frag + OFF_QW, 16, 8, qb, p_q, HH, 1);
    gemm_mma<<<dim3(MT,1), 256>>>(p_q, HH, NN, p_frag + OFF_KWT, 16, 8, nullptr, p_qk, HH, 0);

    float* bufs[2] = { p_hallA, p_hallB };
    const float* hin = p_h0;
    size_t hinStride = 0;
    float* hout = p_hallA;
    for (int i = 0; i < 4; i++){
        gru_fused<<<4*GRU_GRID, 256, GRU_SMEM>>>(hin, hout,
            p_fragW + (size_t)i*12288, p_frag + OFF_WHH,
            bih, bhh, p_rowptr, hinStride);
        hin = hout;
        hinStride = NH;
        hout = bufs[(i + 1) & 1];
    }
    const float* hfinal = hin;

    ln_attn<<<(NN*32 + 255)/256, 256>>>(hfinal, vlnw, vlnb);

    pool_init<<<(BB*HH + 255)/256, 256>>>();
    pool_acc<<<(NN + 63)/64, 128>>>(batch);
    classifier<<<BB, 128>>>(c1w, c1b, c2w, c2b, c3w, c3b, out);
}